// round 13
// baseline (speedup 1.0000x reference)
#include <cuda_runtime.h>
#include <cuda_bf16.h>
#include <cstdint>
#include <math.h>

#define N_SESS   4096
#define T_TRIALS 2048

// 4 warps per session, two-phase decoupled scan. Block = 128 thr = 1 session.
// Warp w owns trials [512w, 512w+512) = 4 chunks of 128.
//  Phase 1: compose quarter total (per-chunk scan -> lane31 totals chained);
//           pack each trial's 2-bit (choice,outcome) index into a register.
//  Phase 2: entering state from SMEM quarter-totals (s0 = 0), coefficients
//           rebuilt from packed bits (no reloads), scan + regen + store.
__global__ __launch_bounds__(128, 8) void qvalue_kernel(
    const float* __restrict__ inp,    // (B, T, 3)
    const float* __restrict__ araw,   // (4,)
    const float* __restrict__ kv,     // (4,)
    float* __restrict__ out)          // (B, T, 2)
{
    __shared__ float tot[4][4];   // [warp][Al, Bl, Ar, Br] quarter totals

    const int tid  = threadIdx.x;
    const int wid  = tid >> 5;
    const int lane = tid & 31;
    const int sess = blockIdx.x;
    const unsigned FULL = 0xFFFFFFFFu;

    // am[i] = 1 - sigmoid(araw[i]),  ak[i] = sigmoid(araw[i]) * k[i]
    float am[4], ak[4];
#pragma unroll
    for (int i = 0; i < 4; i++) {
        float s = 1.0f / (1.0f + expf(-araw[i]));
        am[i] = 1.0f - s;
        ak[i] = s * kv[i];
    }

    // warp's quarter: 512 trials = 384 float4 of input
    const float4* ip = reinterpret_cast<const float4*>(inp) +
                       (size_t)sess * 1536 + wid * 384;
    float4* op = reinterpret_cast<float4*>(out) + (size_t)sess * 1024;

    // ---------------- PHASE 1: quarter total + index packing ----------------
    unsigned pk = 0;                        // 4 chunks x 4 trials x 2 bits
    float TAl = 1.0f, TBl = 0.0f, TAr = 1.0f, TBr = 0.0f;

    int f4 = 3 * lane;
    float4 a0 = ip[f4],      a1 = ip[f4 + 1],  a2 = ip[f4 + 2];
    float4 b0 = ip[f4 + 96], b1 = ip[f4 + 97], b2 = ip[f4 + 98];

#pragma unroll
    for (int c = 0; c < 4; c++) {
        // 2-bit index per trial: idx = 2*chose_left + outcome (exact {0,1} floats)
        unsigned id0 = ((__float_as_uint(a0.x) >> 22) & 2u) | ((__float_as_uint(a0.z) >> 23) & 1u);
        unsigned id1 = ((__float_as_uint(a0.w) >> 22) & 2u) | ((__float_as_uint(a1.y) >> 23) & 1u);
        unsigned id2 = ((__float_as_uint(a1.z) >> 22) & 2u) | ((__float_as_uint(a2.x) >> 23) & 1u);
        unsigned id3 = ((__float_as_uint(a2.y) >> 22) & 2u) | ((__float_as_uint(a2.w) >> 23) & 1u);
        pk |= (id0 | (id1 << 2) | (id2 << 4) | (id3 << 6)) << (8 * c);

        // rotate pipeline; prefetch chunk c+2
        a0 = b0; a1 = b1; a2 = b2;
        if (c + 2 < 4) {
            f4 += 96;
            b0 = ip[f4 + 96]; b1 = ip[f4 + 97]; b2 = ip[f4 + 98];
        }

        // coefficients via SEL on the index bits
        const unsigned idx[4] = {id0, id1, id2, id3};
        float Al[4], Bl[4], Ar[4], Br[4];
#pragma unroll
        for (int j = 0; j < 4; j++) {
            bool po = (idx[j] & 1u);
            bool pc = (idx[j] & 2u);
            float tA = po ? am[0] : am[1];
            float dA = po ? am[2] : am[3];
            float tB = po ? ak[0] : ak[1];
            float dB = po ? ak[2] : ak[3];
            Al[j] = pc ? tA : dA;   Ar[j] = pc ? dA : tA;
            Bl[j] = pc ? tB : dB;   Br[j] = pc ? dB : tB;
        }

        // compose lane's 4 trials
        float Acl = Al[0], Bcl = Bl[0], Acr = Ar[0], Bcr = Br[0];
#pragma unroll
        for (int j = 1; j < 4; j++) {
            Bcl = fmaf(Al[j], Bcl, Bl[j]);  Acl = Al[j] * Acl;
            Bcr = fmaf(Ar[j], Bcr, Br[j]);  Acr = Ar[j] * Acr;
        }
        // inclusive warp scan; lane 31 = chunk total
#pragma unroll
        for (int d = 1; d < 32; d <<= 1) {
            float Apl = __shfl_up_sync(FULL, Acl, d);
            float Bpl = __shfl_up_sync(FULL, Bcl, d);
            float Apr = __shfl_up_sync(FULL, Acr, d);
            float Bpr = __shfl_up_sync(FULL, Bcr, d);
            if (lane >= d) {
                Bcl = fmaf(Acl, Bpl, Bcl);  Acl *= Apl;
                Bcr = fmaf(Acr, Bpr, Bcr);  Acr *= Apr;
            }
        }
        float A31l = __shfl_sync(FULL, Acl, 31);
        float B31l = __shfl_sync(FULL, Bcl, 31);
        float A31r = __shfl_sync(FULL, Acr, 31);
        float B31r = __shfl_sync(FULL, Bcr, 31);
        // chain chunk total onto quarter total (chunk applied after)
        TBl = fmaf(A31l, TBl, B31l);  TAl = A31l * TAl;
        TBr = fmaf(A31r, TBr, B31r);  TAr = A31r * TAr;
    }

    if (lane == 0) {
        tot[wid][0] = TAl;  tot[wid][1] = TBl;
        tot[wid][2] = TAr;  tot[wid][3] = TBr;
    }
    __syncthreads();

    // ---------------- PHASE 2: entering state + outputs ----------------
    float sl = 0.0f, sr = 0.0f;
#pragma unroll
    for (int k = 0; k < 3; k++) {
        if (k < wid) {
            sl = fmaf(tot[k][0], sl, tot[k][1]);
            sr = fmaf(tot[k][2], sr, tot[k][3]);
        }
    }

#pragma unroll
    for (int c = 0; c < 4; c++) {
        const unsigned byte = (pk >> (8 * c)) & 0xFFu;
        float Al[4], Bl[4], Ar[4], Br[4];
#pragma unroll
        for (int j = 0; j < 4; j++) {
            unsigned idx = (byte >> (2 * j)) & 3u;
            bool po = (idx & 1u);
            bool pc = (idx & 2u);
            float tA = po ? am[0] : am[1];
            float dA = po ? am[2] : am[3];
            float tB = po ? ak[0] : ak[1];
            float dB = po ? ak[2] : ak[3];
            Al[j] = pc ? tA : dA;   Ar[j] = pc ? dA : tA;
            Bl[j] = pc ? tB : dB;   Br[j] = pc ? dB : tB;
        }

        float Acl = Al[0], Bcl = Bl[0], Acr = Ar[0], Bcr = Br[0];
#pragma unroll
        for (int j = 1; j < 4; j++) {
            Bcl = fmaf(Al[j], Bcl, Bl[j]);  Acl = Al[j] * Acl;
            Bcr = fmaf(Ar[j], Bcr, Br[j]);  Acr = Ar[j] * Acr;
        }
#pragma unroll
        for (int d = 1; d < 32; d <<= 1) {
            float Apl = __shfl_up_sync(FULL, Acl, d);
            float Bpl = __shfl_up_sync(FULL, Bcl, d);
            float Apr = __shfl_up_sync(FULL, Acr, d);
            float Bpr = __shfl_up_sync(FULL, Bcr, d);
            if (lane >= d) {
                Bcl = fmaf(Acl, Bpl, Bcl);  Acl *= Apl;
                Bcr = fmaf(Acr, Bpr, Bcr);  Acr *= Apr;
            }
        }

        // early next-state handoff (off the regen path)
        float A31l = __shfl_sync(FULL, Acl, 31);
        float B31l = __shfl_sync(FULL, Bcl, 31);
        float A31r = __shfl_sync(FULL, Acr, 31);
        float B31r = __shfl_sync(FULL, Bcr, 31);
        float nsl = fmaf(A31l, sl, B31l);
        float nsr = fmaf(A31r, sr, B31r);

        float Ael = __shfl_up_sync(FULL, Acl, 1);
        float Bel = __shfl_up_sync(FULL, Bcl, 1);
        float Aer = __shfl_up_sync(FULL, Acr, 1);
        float Ber = __shfl_up_sync(FULL, Bcr, 1);
        if (lane == 0) { Ael = 1.0f; Bel = 0.0f; Aer = 1.0f; Ber = 0.0f; }
        float tl = fmaf(Ael, sl, Bel);
        float tr = fmaf(Aer, sr, Ber);

        sl = nsl;  sr = nsr;

        float4 o0, o1;
        tl = fmaf(Al[0], tl, Bl[0]);  tr = fmaf(Ar[0], tr, Br[0]);
        o0.x = tl;  o0.y = tr;
        tl = fmaf(Al[1], tl, Bl[1]);  tr = fmaf(Ar[1], tr, Br[1]);
        o0.z = tl;  o0.w = tr;
        tl = fmaf(Al[2], tl, Bl[2]);  tr = fmaf(Ar[2], tr, Br[2]);
        o1.x = tl;  o1.y = tr;
        tl = fmaf(Al[3], tl, Bl[3]);  tr = fmaf(Ar[3], tr, Br[3]);
        o1.z = tl;  o1.w = tr;

        const int ofb = wid * 256 + c * 64 + 2 * lane;
        op[ofb]     = o0;
        op[ofb + 1] = o1;
    }
}

extern "C" void kernel_launch(void* const* d_in, const int* in_sizes, int n_in,
                              void* d_out, int out_size) {
    const float* inp  = (const float*)d_in[0];   // (4096, 2048, 3) f32
    const float* araw = (const float*)d_in[1];   // (4,) f32
    const float* kv   = (const float*)d_in[2];   // (4,) f32
    float* out = (float*)d_out;                  // (4096, 2048, 2) f32

    // one block per session, 4 warps per session -> 16384 warps total
    qvalue_kernel<<<N_SESS, 128>>>(inp, araw, kv, out);
}

// round 14
// speedup vs baseline: 1.1143x; 1.1143x over previous
#include <cuda_runtime.h>
#include <cuda_bf16.h>
#include <cstdint>
#include <math.h>

#define N_SESS   4096
#define T_TRIALS 2048

// Warp-per-session affine scan — the proven R3 kernel (4 trials/lane,
// SEL coefficients, 16 chunks, 128-thr blocks) with exactly ONE change:
// depth-3 load pipeline (9 float4 in flight), so prefetch lead time
// (~600 cyc) exceeds DRAM latency (~380-580 cyc) instead of undershooting
// it (~300 cyc at depth-2).
__global__ __launch_bounds__(128) void qvalue_kernel(
    const float* __restrict__ inp,    // (B, T, 3)
    const float* __restrict__ araw,   // (4,)
    const float* __restrict__ kv,     // (4,)
    float* __restrict__ out)          // (B, T, 2)
{
    const int gtid = blockIdx.x * blockDim.x + threadIdx.x;
    const int warp = gtid >> 5;
    const int lane = gtid & 31;
    if (warp >= N_SESS) return;

    // am[i] = 1 - sigmoid(araw[i]),  ak[i] = sigmoid(araw[i]) * k[i]
    float am[4], ak[4];
#pragma unroll
    for (int i = 0; i < 4; i++) {
        float s = 1.0f / (1.0f + expf(-araw[i]));
        am[i] = 1.0f - s;
        ak[i] = s * kv[i];
    }

    const float4* ip = reinterpret_cast<const float4*>(inp + (size_t)warp * T_TRIALS * 3);
    float4*       op = reinterpret_cast<float4*>(out + (size_t)warp * T_TRIALS * 2);

    float sl = 0.0f, sr = 0.0f;
    const unsigned FULL = 0xFFFFFFFFu;
    const int F4_CHUNK = 96;   // float4 per 128-trial chunk

    // depth-3 pipeline: chunks c, c+1, c+2 resident
    int f4 = 3 * lane;
    float4 c0a = ip[f4], c0b = ip[f4 + 1], c0c = ip[f4 + 2];
    f4 += F4_CHUNK;
    float4 c1a = ip[f4], c1b = ip[f4 + 1], c1c = ip[f4 + 2];
    f4 += F4_CHUNK;
    float4 c2a = ip[f4], c2b = ip[f4 + 1], c2c = ip[f4 + 2];

#pragma unroll 2
    for (int chunk = 0; chunk < 16; chunk++) {
        const int t = chunk * 128 + 4 * lane;

        // unpack current chunk: chose_left and outcome
        float cl[4] = {c0a.x, c0a.w, c0b.z, c0c.y};
        float oo[4] = {c0a.z, c0b.y, c0c.x, c0c.w};

        // rotate pipeline and issue loads for chunk+3 (overlap with scan)
        c0a = c1a; c0b = c1b; c0c = c1c;
        c1a = c2a; c1b = c2b; c1c = c2c;
        if (chunk + 3 < 16) {
            f4 += F4_CHUNK;
            c2a = ip[f4]; c2b = ip[f4 + 1]; c2c = ip[f4 + 2];
        }

        // per-trial affine coefficients via SEL (inputs are exact {0,1})
        float Al[4], Bl[4], Ar[4], Br[4];
#pragma unroll
        for (int j = 0; j < 4; j++) {
            bool po = (oo[j] != 0.0f);
            bool pc = (cl[j] != 0.0f);
            float tA = po ? am[0] : am[1];   // "same" side: rew/unrew
            float dA = po ? am[2] : am[3];   // "diff" side
            float tB = po ? ak[0] : ak[1];
            float dB = po ? ak[2] : ak[3];
            Al[j] = pc ? tA : dA;   Ar[j] = pc ? dA : tA;
            Bl[j] = pc ? tB : dB;   Br[j] = pc ? dB : tB;
        }

        // compose lane's 4 trials (trial 0 first): A=A2*A1, B=A2*B1+B2
        float Acl = Al[0], Bcl = Bl[0], Acr = Ar[0], Bcr = Br[0];
#pragma unroll
        for (int j = 1; j < 4; j++) {
            Bcl = fmaf(Al[j], Bcl, Bl[j]);  Acl = Al[j] * Acl;
            Bcr = fmaf(Ar[j], Bcr, Br[j]);  Acr = Ar[j] * Acr;
        }

        // warp inclusive scan (lane 0 earliest)
#pragma unroll
        for (int d = 1; d < 32; d <<= 1) {
            float Apl = __shfl_up_sync(FULL, Acl, d);
            float Bpl = __shfl_up_sync(FULL, Bcl, d);
            float Apr = __shfl_up_sync(FULL, Acr, d);
            float Bpr = __shfl_up_sync(FULL, Bcr, d);
            if (lane >= d) {
                Bcl = fmaf(Acl, Bpl, Bcl);  Acl *= Apl;
                Bcr = fmaf(Acr, Bpr, Bcr);  Acr *= Apr;
            }
        }

        // exclusive prefix -> state entering this lane's trials
        float Ael = __shfl_up_sync(FULL, Acl, 1);
        float Bel = __shfl_up_sync(FULL, Bcl, 1);
        float Aer = __shfl_up_sync(FULL, Acr, 1);
        float Ber = __shfl_up_sync(FULL, Bcr, 1);
        if (lane == 0) { Ael = 1.0f; Bel = 0.0f; Aer = 1.0f; Ber = 0.0f; }
        float tl = fmaf(Ael, sl, Bel);
        float tr = fmaf(Aer, sr, Ber);

        // regenerate 4 per-trial outputs
        float4 o0, o1;
        tl = fmaf(Al[0], tl, Bl[0]);  tr = fmaf(Ar[0], tr, Br[0]);
        o0.x = tl;  o0.y = tr;
        tl = fmaf(Al[1], tl, Bl[1]);  tr = fmaf(Ar[1], tr, Br[1]);
        o0.z = tl;  o0.w = tr;
        tl = fmaf(Al[2], tl, Bl[2]);  tr = fmaf(Ar[2], tr, Br[2]);
        o1.x = tl;  o1.y = tr;
        tl = fmaf(Al[3], tl, Bl[3]);  tr = fmaf(Ar[3], tr, Br[3]);
        o1.z = tl;  o1.w = tr;

        const int ofb = (t * 2) >> 2;
        op[ofb]     = o0;
        op[ofb + 1] = o1;

        // session state = lane31's state after trial 127
        sl = __shfl_sync(FULL, tl, 31);
        sr = __shfl_sync(FULL, tr, 31);
    }
}

extern "C" void kernel_launch(void* const* d_in, const int* in_sizes, int n_in,
                              void* d_out, int out_size) {
    const float* inp  = (const float*)d_in[0];   // (4096, 2048, 3) f32
    const float* araw = (const float*)d_in[1];   // (4,) f32
    const float* kv   = (const float*)d_in[2];   // (4,) f32
    float* out = (float*)d_out;                  // (4096, 2048, 2) f32

    // 4096 warps in 128-thread blocks -> 1024 blocks
    qvalue_kernel<<<1024, 128>>>(inp, araw, kv, out);
}